// round 1
// baseline (speedup 1.0000x reference)
#include <cuda_runtime.h>
#include <cuda_bf16.h>

// Sparsemax over rows of length 2048 via Michelot's threshold iteration.
// One CTA per row, row resident in registers, single read + single write.

#define ROWLEN  2048
#define THREADS 256
#define VPT     (ROWLEN / THREADS)   // 8 values per thread
#define NWARP   (THREADS / 32)       // 8 warps

__global__ __launch_bounds__(THREADS, 8)
void sparsemax_kernel(const float* __restrict__ z, float* __restrict__ out) {
    const long long row = blockIdx.x;
    const float4* __restrict__ z4   = reinterpret_cast<const float4*>(z + row * ROWLEN);
    float4* __restrict__       out4 = reinterpret_cast<float4*>(out + row * ROWLEN);
    const int tid  = threadIdx.x;
    const int lane = tid & 31;
    const int wid  = tid >> 5;

    // ---- load 8 fp32 per thread (2x float4, coalesced) ----
    float4 a = z4[tid];
    float4 b = z4[tid + THREADS];
    float v[VPT] = {a.x, a.y, a.z, a.w, b.x, b.y, b.z, b.w};

    __shared__ float s_sum[NWARP];
    __shared__ float s_cnt[NWARP];
    __shared__ float s_tau;
    __shared__ int   s_k;

    // ---- initial tau from full support: tau0 = (sum - 1)/n ----
    float tau;
    {
        float s = 0.0f;
        #pragma unroll
        for (int i = 0; i < VPT; i++) s += v[i];
        #pragma unroll
        for (int o = 16; o > 0; o >>= 1) s += __shfl_xor_sync(0xffffffffu, s, o);
        if (lane == 0) s_sum[wid] = s;
        __syncthreads();
        if (tid == 0) {
            float tot = 0.0f;
            #pragma unroll
            for (int w = 0; w < NWARP; w++) tot += s_sum[w];
            s_tau = (tot - 1.0f) * (1.0f / (float)ROWLEN);
        }
        __syncthreads();
        tau = s_tau;
    }

    // ---- Michelot iteration: active set shrinks strictly until fixed point ----
    int k_prev = ROWLEN;
    #pragma unroll 1
    for (int it = 0; it < 64; it++) {
        float s = 0.0f, c = 0.0f;
        #pragma unroll
        for (int i = 0; i < VPT; i++) {
            bool act = v[i] > tau;
            s += act ? v[i] : 0.0f;
            c += act ? 1.0f : 0.0f;
        }
        #pragma unroll
        for (int o = 16; o > 0; o >>= 1) {
            s += __shfl_xor_sync(0xffffffffu, s, o);
            c += __shfl_xor_sync(0xffffffffu, c, o);
        }
        if (lane == 0) { s_sum[wid] = s; s_cnt[wid] = c; }
        __syncthreads();
        if (tid == 0) {
            float ts = 0.0f, tc = 0.0f;
            #pragma unroll
            for (int w = 0; w < NWARP; w++) { ts += s_sum[w]; tc += s_cnt[w]; }
            s_tau = (ts - 1.0f) / tc;
            s_k   = (int)tc;
        }
        __syncthreads();
        tau = s_tau;
        int k = s_k;
        if (k == k_prev) break;   // uniform (read from shared) -> no divergence
        k_prev = k;
    }

    // ---- project: max(z - tau, 0), single coalesced write ----
    float4 o0, o1;
    o0.x = fmaxf(v[0] - tau, 0.0f);
    o0.y = fmaxf(v[1] - tau, 0.0f);
    o0.z = fmaxf(v[2] - tau, 0.0f);
    o0.w = fmaxf(v[3] - tau, 0.0f);
    o1.x = fmaxf(v[4] - tau, 0.0f);
    o1.y = fmaxf(v[5] - tau, 0.0f);
    o1.z = fmaxf(v[6] - tau, 0.0f);
    o1.w = fmaxf(v[7] - tau, 0.0f);
    out4[tid]           = o0;
    out4[tid + THREADS] = o1;
}

extern "C" void kernel_launch(void* const* d_in, const int* in_sizes, int n_in,
                              void* d_out, int out_size) {
    const float* z = (const float*)d_in[0];
    float* out = (float*)d_out;
    int rows = in_sizes[0] / ROWLEN;
    sparsemax_kernel<<<rows, THREADS>>>(z, out);
}

// round 2
// speedup vs baseline: 2.2367x; 2.2367x over previous
#include <cuda_runtime.h>
#include <cuda_bf16.h>

// Sparsemax rows of 2048 fp32. Key fact: tau* >= z_max - 1, so only elements
// > z_max - 1 can be in the support. For Gaussian rows that is ~4-30 elements.
// Main path: max-reduce, candidate gather, tiny warp-local Michelot solve,
// projection write. ~5 ALU ops/element instead of ~25.

#define ROWLEN  2048
#define THREADS 256
#define VPT     (ROWLEN / THREADS)   // 8
#define NWARP   (THREADS / 32)       // 8
#define CAP     256                  // candidate buffer capacity
#define NEG_INF (-3.0e38f)

__global__ __launch_bounds__(THREADS, 8)
void sparsemax_kernel(const float* __restrict__ z, float* __restrict__ out) {
    const long long row = blockIdx.x;
    const float4* __restrict__ z4   = reinterpret_cast<const float4*>(z + row * ROWLEN);
    float4* __restrict__       out4 = reinterpret_cast<float4*>(out + row * ROWLEN);
    const int tid  = threadIdx.x;
    const int lane = tid & 31;
    const int wid  = tid >> 5;

    __shared__ float s_red[NWARP];
    __shared__ float s_cnt[NWARP];
    __shared__ float s_cand[CAP];
    __shared__ int   s_n;
    __shared__ float s_tau;

    // ---- load row into registers (coalesced float4) ----
    float4 a = z4[tid];
    float4 b = z4[tid + THREADS];
    float v[VPT] = {a.x, a.y, a.z, a.w, b.x, b.y, b.z, b.w};

    if (tid == 0) s_n = 0;

    // ---- block max ----
    float m = v[0];
    #pragma unroll
    for (int i = 1; i < VPT; i++) m = fmaxf(m, v[i]);
    #pragma unroll
    for (int o = 16; o > 0; o >>= 1) m = fmaxf(m, __shfl_xor_sync(0xffffffffu, m, o));
    if (lane == 0) s_red[wid] = m;
    __syncthreads();
    float M = s_red[0];
    #pragma unroll
    for (int w = 1; w < NWARP; w++) M = fmaxf(M, s_red[w]);

    const float theta = M - 1.0f;   // tau* >= theta

    // ---- gather candidates z > theta into shared buffer ----
    #pragma unroll
    for (int i = 0; i < VPT; i++) {
        if (v[i] > theta) {
            int idx = atomicAdd(&s_n, 1);
            if (idx < CAP) s_cand[idx] = v[i];
        }
    }
    __syncthreads();
    const int n = s_n;

    if (n <= CAP) {
        // ---- warp 0 solves Michelot on the tiny candidate set ----
        if (wid == 0) {
            float c[CAP / 32];
            #pragma unroll
            for (int i = 0; i < CAP / 32; i++) {
                int idx = lane + 32 * i;
                c[i] = (idx < n) ? s_cand[idx] : NEG_INF;
            }
            float tau = theta;
            int prev = n + 1;   // force at least one iteration
            #pragma unroll 1
            for (int it = 0; it < 64; it++) {
                float s = 0.0f, cnt = 0.0f;
                #pragma unroll
                for (int i = 0; i < CAP / 32; i++) {
                    bool act = c[i] > tau;
                    s   += act ? c[i] : 0.0f;
                    cnt += act ? 1.0f : 0.0f;
                }
                #pragma unroll
                for (int o = 16; o > 0; o >>= 1) {
                    s   += __shfl_xor_sync(0xffffffffu, s, o);
                    cnt += __shfl_xor_sync(0xffffffffu, cnt, o);
                }
                tau = (s - 1.0f) / cnt;
                int k = (int)cnt;
                if (k == prev) break;
                prev = k;
            }
            if (lane == 0) s_tau = tau;
        }
        __syncthreads();
    } else {
        // ---- fallback: full-block Michelot over register-resident row ----
        // (unreachable for Gaussian inputs; kept for general correctness)
        float tau;
        {
            float s = 0.0f;
            #pragma unroll
            for (int i = 0; i < VPT; i++) s += v[i];
            #pragma unroll
            for (int o = 16; o > 0; o >>= 1) s += __shfl_xor_sync(0xffffffffu, s, o);
            if (lane == 0) s_red[wid] = s;
            __syncthreads();
            if (tid == 0) {
                float tot = 0.0f;
                #pragma unroll
                for (int w = 0; w < NWARP; w++) tot += s_red[w];
                s_tau = (tot - 1.0f) * (1.0f / (float)ROWLEN);
            }
            __syncthreads();
            tau = s_tau;
        }
        int k_prev = ROWLEN;
        #pragma unroll 1
        for (int it = 0; it < 64; it++) {
            float s = 0.0f, cf = 0.0f;
            #pragma unroll
            for (int i = 0; i < VPT; i++) {
                bool act = v[i] > tau;
                s  += act ? v[i] : 0.0f;
                cf += act ? 1.0f : 0.0f;
            }
            #pragma unroll
            for (int o = 16; o > 0; o >>= 1) {
                s  += __shfl_xor_sync(0xffffffffu, s, o);
                cf += __shfl_xor_sync(0xffffffffu, cf, o);
            }
            if (lane == 0) { s_red[wid] = s; s_cnt[wid] = cf; }
            __syncthreads();
            if (tid == 0) {
                float ts = 0.0f, tc = 0.0f;
                #pragma unroll
                for (int w = 0; w < NWARP; w++) { ts += s_red[w]; tc += s_cnt[w]; }
                s_tau = (ts - 1.0f) / tc;
                s_cnt[0] = tc;
            }
            __syncthreads();
            tau = s_tau;
            int k = (int)s_cnt[0];
            __syncthreads();
            if (k == k_prev) break;
            k_prev = k;
        }
    }

    const float tau = s_tau;

    // ---- project and store ----
    float4 o0, o1;
    o0.x = fmaxf(v[0] - tau, 0.0f);
    o0.y = fmaxf(v[1] - tau, 0.0f);
    o0.z = fmaxf(v[2] - tau, 0.0f);
    o0.w = fmaxf(v[3] - tau, 0.0f);
    o1.x = fmaxf(v[4] - tau, 0.0f);
    o1.y = fmaxf(v[5] - tau, 0.0f);
    o1.z = fmaxf(v[6] - tau, 0.0f);
    o1.w = fmaxf(v[7] - tau, 0.0f);
    out4[tid]           = o0;
    out4[tid + THREADS] = o1;
}

extern "C" void kernel_launch(void* const* d_in, const int* in_sizes, int n_in,
                              void* d_out, int out_size) {
    const float* z = (const float*)d_in[0];
    float* out = (float*)d_out;
    int rows = in_sizes[0] / ROWLEN;
    sparsemax_kernel<<<rows, THREADS>>>(z, out);
}